// round 15
// baseline (speedup 1.0000x reference)
#include <cuda_runtime.h>
#include <cuda_fp16.h>
#include <math.h>

#define N_MET   100000
#define N_RXN   200000
#define E_SUB   400000
#define E_PROD  400000
#define HIDDEN  128
#define MSG     64
#define DT      0.01f

#define SCAN_BS 512
#define NB1     ((N_RXN + SCAN_BS - 1) / SCAN_BS)   // 391

#define LDH 136     // smem stride (halves) for T and M tiles (conflict-free)
#define K2_TILE 64
#define K2_NTILES (N_RXN / K2_TILE)                 // 3125, exact
#define K2_GRID  296                                // 2 CTAs/SM, one wave
#define K2_THREADS 512

#define HIST_B    ((E_SUB + 255) / 256)             // 1563
#define CONTRIB_B ((E_SUB + E_PROD + 255) / 256)    // 3125

// gemm2 smem: c1/V2/bb (1536B) + scnt/sext double (1024B) + P (1536B)
//           + T double (2*64*LDH*2 = 34816B) + M (128*LDH*2 = 34816B)
#define G2_SMEM_BYTES (1536 + 1024 + 1536 + 2 * K2_TILE * LDH * 2 + HIDDEN * LDH * 2)

// ---------------- scratch (device globals; no allocation allowed) -------------
// g_cnt and g_sstate start zero (BSS) and are re-zeroed at the graph tail each
// call, so every kernel_launch invocation sees the same initial state.
__device__ int                g_cnt[N_RXN];
__device__ unsigned long long g_sstate[NB1];        // lookback scan state
__device__ int                g_start[N_RXN];
__device__ int                g_cursor[N_RXN];
__device__ int                g_eidx[E_SUB];
__device__ __half             g_Mh[HIDDEN * HIDDEN];   // fp16 W2@V1, [n][k] layout
__device__ float              g_bb[HIDDEN];            // b2 @ V1
__device__ __half             g_T[(size_t)N_RXN * HIDDEN];  // 51.2MB, L2-resident
__device__ float              g_cntf[N_RXN];
__device__ float              g_exts[N_RXN];
__device__ float              g_v[N_RXN];
__device__ float              g_rscale[N_RXN];
__device__ float              g_totcons[N_MET];

#define ST_AGG (1ULL << 62)
#define ST_PRE (2ULL << 62)
#define ST_VAL 0x3FFFFFFFFFFFFFFFULL

__device__ __forceinline__ float tanh_fast(float x) {
    float y; asm("tanh.approx.f32 %0, %1;" : "=f"(y) : "f"(x)); return y;
}
__device__ __forceinline__ unsigned smem_u32(const void* p) {
    return (unsigned)__cvta_generic_to_shared(p);
}
#define LDSM_X4(r0, r1, r2, r3, addr) \
    asm volatile("ldmatrix.sync.aligned.m8n8.x4.shared.b16 {%0,%1,%2,%3}, [%4];" \
                 : "=r"(r0), "=r"(r1), "=r"(r2), "=r"(r3) : "r"(addr))
#define LDSM_X2(r0, r1, addr) \
    asm volatile("ldmatrix.sync.aligned.m8n8.x2.shared.b16 {%0,%1}, [%2];" \
                 : "=r"(r0), "=r"(r1) : "r"(addr))
#define CP_ASYNC16(dst, src) \
    asm volatile("cp.async.ca.shared.global [%0], [%1], 16;" :: "r"(dst), "l"(src) : "memory")
#define CP_ASYNC4(dst, src) \
    asm volatile("cp.async.ca.shared.global [%0], [%1], 4;" :: "r"(dst), "l"(src) : "memory")
#define CP_COMMIT() asm volatile("cp.async.commit_group;" ::: "memory")
#define CP_WAIT0()  asm volatile("cp.async.wait_group 0;" ::: "memory")

// ---------------- L1: histogram + weight folding + zeroing (fused) ------------
__global__ void k_hist_init(const int*   __restrict__ rxn_sub,
                            const float* __restrict__ W2,
                            const float* __restrict__ V1,
                            const float* __restrict__ b2,
                            float* __restrict__ out)
{
    int blk = blockIdx.x, tid = threadIdx.x;
    if (blk < HIST_B) {
        int e = blk * 256 + tid;
        if (e < E_SUB) atomicAdd(&g_cnt[rxn_sub[e]], 1);
    } else if (blk < HIST_B + HIDDEN) {
        if (tid < HIDDEN) {
            int j = blk - HIST_B;   // k-dim index
            float acc = 0.f;
            for (int k = 0; k < MSG; k++)
                acc = fmaf(W2[j * MSG + k], V1[k * HIDDEN + tid], acc);
            g_Mh[tid * HIDDEN + j] = __float2half_rn(acc);   // [n][k] (B col-major)
        }
    } else if (blk == HIST_B + HIDDEN) {
        if (tid < HIDDEN) {
            float acc = 0.f;
            for (int k = 0; k < MSG; k++)
                acc = fmaf(b2[k], V1[k * HIDDEN + tid], acc);
            g_bb[tid] = acc;
        }
    } else {
        int i = (blk - (HIST_B + HIDDEN + 1)) * 256 + tid;
        int stride = (gridDim.x - (HIST_B + HIDDEN + 1)) * 256;
        for (int p = i; p < N_MET; p += stride) { g_totcons[p] = 0.f; out[p] = 0.f; }
    }
}

// ---------------- L2: single-pass decoupled-lookback exclusive scan -----------
__global__ void k_scan_lb() {
    __shared__ int s[SCAN_BS];
    __shared__ int s_running;
    int b = blockIdx.x, t = threadIdx.x;
    int i = b * SCAN_BS + t;
    int v = (i < N_RXN) ? g_cnt[i] : 0;
    s[t] = v; __syncthreads();
    for (int off = 1; off < SCAN_BS; off <<= 1) {
        int xx = (t >= off) ? s[t - off] : 0;
        __syncthreads();
        s[t] += xx;
        __syncthreads();
    }
    if (t == 0) {
        unsigned long long total = (unsigned long long)s[SCAN_BS - 1];
        if (b == 0) {
            atomicExch(&g_sstate[0], ST_PRE | total);
            s_running = 0;
        } else {
            atomicExch(&g_sstate[b], ST_AGG | total);
            unsigned long long run = 0;
            for (int pb = b - 1; pb >= 0; pb--) {
                unsigned long long st;
                do { st = atomicAdd(&g_sstate[pb], 0ULL); } while ((st >> 62) == 0ULL);
                run += st & ST_VAL;
                if ((st >> 62) == 2ULL) break;
            }
            atomicExch(&g_sstate[b], ST_PRE | (run + total));
            s_running = (int)run;
        }
    }
    __syncthreads();
    if (i < N_RXN) {
        int st = s_running + s[t] - v;
        g_start[i]  = st;
        g_cursor[i] = st;
    }
}

// ---------------- L3: scatter edge ids into CSR order -------------------------
__global__ void k_scatter(const int* __restrict__ rxn_sub) {
    int e = blockIdx.x * blockDim.x + threadIdx.x;
    if (e >= E_SUB) return;
    int pos = atomicAdd(&g_cursor[rxn_sub[e]], 1);
    g_eidx[pos] = e;
}

// ---------------- L4: layer-1, warp-per-reaction (no barriers) ----------------
// Lane l holds units 4l..4l+3 (U,W,b in regs). Edge loads are broadcast
// (all lanes same address -> 1 wavefront). Writes T row (256B coalesced).
__global__ __launch_bounds__(256)
void k_layer1(const float* __restrict__ x,
              const int*   __restrict__ met_sub,
              const float* __restrict__ sto_sub,
              const float* __restrict__ W1,
              const float* __restrict__ b1)
{
    int gw = (blockIdx.x * 256 + threadIdx.x) >> 5;
    int lane = threadIdx.x & 31;
    if (gw >= N_RXN) return;

    float4 u4 = reinterpret_cast<const float4*>(W1)[lane];
    float4 w4 = reinterpret_cast<const float4*>(W1 + HIDDEN)[lane];
    float4 b4 = reinterpret_cast<const float4*>(b1)[lane];

    int s = g_start[gw], c = g_cnt[gw];
    float a0 = 0.f, a1 = 0.f, a2 = 0.f, a3 = 0.f, ext = 0.f;
    for (int l = 0; l < c; l++) {
        int   idx = g_eidx[s + l];
        int   met = met_sub[idx];
        float a   = x[met * 8 + 3];
        float st  = sto_sub[idx];
        ext += x[met * 8 + 4];
        a0 += tanh_fast(fmaf(a, u4.x, fmaf(st, w4.x, b4.x)));
        a1 += tanh_fast(fmaf(a, u4.y, fmaf(st, w4.y, b4.y)));
        a2 += tanh_fast(fmaf(a, u4.z, fmaf(st, w4.z, b4.z)));
        a3 += tanh_fast(fmaf(a, u4.w, fmaf(st, w4.w, b4.w)));
    }
    __half2 h0 = __floats2half2_rn(a0, a1);
    __half2 h1 = __floats2half2_rn(a2, a3);
    float2 packed = make_float2(__uint_as_float(*(unsigned*)&h0),
                                __uint_as_float(*(unsigned*)&h1));
    reinterpret_cast<float2*>(g_T + (size_t)gw * HIDDEN)[lane] = packed;
    if (lane == 0) { g_cntf[gw] = (float)c; g_exts[gw] = ext; }
}

// ---------------- L5: dense fp16 GEMM + epilogue (cp.async pipelined) ---------
__global__ __launch_bounds__(K2_THREADS, 2)
void k_gemm2(const float* __restrict__ c1v,
             const float* __restrict__ V2,
             const float* __restrict__ c2,
             const float* __restrict__ log_k)
{
    extern __shared__ float sm[];
    float*    sc1  = sm;                               // 128
    float*    sV2  = sc1 + 128;                        // 128
    float*    sbb  = sV2 + 128;                        // 128
    float*    scnt = sbb + 128;                        // 2 x 64
    float*    sext = scnt + 128;                       // 2 x 64
    float*    sP   = sext + 128;                       // 384
    __half*   sTh  = (__half*)(sP + 384);              // 2 x 64 x LDH halves
    __half*   sMh  = sTh + 2 * K2_TILE * LDH;          // 128 x LDH halves

    int tid = threadIdx.x;
    int w = tid >> 5, lane = tid & 31, gid = lane >> 2, tig = lane & 3;
    int wr = w & 3;
    int s_set = w >> 2;
    int nt0 = s_set * 4;

    if (tid < 128) {
        sc1[tid] = c1v[tid];
        sV2[tid] = V2[tid];
        sbb[tid] = g_bb[tid];
    }
    for (int i = tid; i < HIDDEN * HIDDEN / 2; i += K2_THREADS) {
        int row = i >> 6, col2 = i & 63;
        reinterpret_cast<__half2*>(sMh)[row * (LDH / 2) + col2] =
            reinterpret_cast<const __half2*>(g_Mh)[i];
    }
    float c2s = c2[0];

    unsigned tbase0 = smem_u32(sTh);
    unsigned tbase1 = smem_u32(sTh + K2_TILE * LDH);

    // B ldmatrix addresses (fixed)
    unsigned baddr[4];
    #pragma unroll
    for (int j = 0; j < 4; j++)
        baddr[j] = smem_u32(sMh) +
            ((((nt0 + j) * 8 + (lane & 7)) * LDH + 8 * ((lane >> 3) & 1)) << 1);
    // A ldmatrix offset within a T buffer
    unsigned aoff = (((wr * 16 + (lane & 15)) * LDH + 8 * (lane >> 4)) << 1);

    // tile T copy: 1024 16B chunks; thread does chunks tid, tid+512
    // chunk c -> row = c>>4, seg = c&15
    auto stage_tile = [&](int tile, int buf) {
        const __half* src = g_T + (size_t)tile * K2_TILE * HIDDEN;
        unsigned dstb = buf ? tbase1 : tbase0;
        #pragma unroll
        for (int h = 0; h < 2; h++) {
            int ch = tid + h * 512;
            int row = ch >> 4, seg = ch & 15;
            CP_ASYNC16(dstb + ((row * LDH + seg * 8) << 1),
                       src + row * HIDDEN + seg * 8);
        }
        if (tid < 64)
            CP_ASYNC4(smem_u32(scnt + buf * 64 + tid), g_cntf + tile * K2_TILE + tid);
        else if (tid < 128)
            CP_ASYNC4(smem_u32(sext + buf * 64 + (tid - 64)),
                      g_exts + tile * K2_TILE + (tid - 64));
    };

    // prologue
    stage_tile(blockIdx.x, 0);
    CP_COMMIT();
    CP_WAIT0();
    __syncthreads();

    int pb = 0;
    for (int tile = blockIdx.x; tile < K2_NTILES; tile += K2_GRID) {
        int tnext = tile + K2_GRID;
        if (tnext < K2_NTILES) {
            stage_tile(tnext, pb ^ 1);
            CP_COMMIT();
        }

        unsigned abase = (pb ? tbase1 : tbase0) + aoff;
        float* scntc = scnt + pb * 64;
        float* sextc = sext + pb * 64;

        float accm[4][4];
        #pragma unroll
        for (int j = 0; j < 4; j++) {
            accm[j][0] = 0.f; accm[j][1] = 0.f; accm[j][2] = 0.f; accm[j][3] = 0.f;
        }

        #pragma unroll
        for (int kt = 0; kt < 8; kt++) {
            unsigned koff = kt * 32;
            unsigned a0, a1, a2, a3;
            LDSM_X4(a0, a1, a2, a3, abase + koff);
            #pragma unroll
            for (int j = 0; j < 4; j++) {
                unsigned b0, b1;
                LDSM_X2(b0, b1, baddr[j] + koff);
                asm volatile(
                    "mma.sync.aligned.m16n8k16.row.col.f32.f16.f16.f32 "
                    "{%0,%1,%2,%3}, {%4,%5,%6,%7}, {%8,%9}, {%0,%1,%2,%3};"
                    : "+f"(accm[j][0]), "+f"(accm[j][1]), "+f"(accm[j][2]), "+f"(accm[j][3])
                    : "r"(a0), "r"(a1), "r"(a2), "r"(a3), "r"(b0), "r"(b1));
            }
        }

        float cnt0 = scntc[wr * 16 + gid], cnt1 = scntc[wr * 16 + gid + 8];
        float acc0 = 0.f, acc1 = 0.f;
        #pragma unroll
        for (int j = 0; j < 4; j++) {
            int n0 = (nt0 + j) * 8;
            int col0 = n0 + 2 * tig, col1 = col0 + 1;
            float bi0 = sc1[col0], bi1 = sc1[col1];
            float bb0 = sbb[col0], bb1 = sbb[col1];
            float v0  = sV2[col0], v1  = sV2[col1];
            acc0 += tanh_fast(fmaf(cnt0, bb0, accm[j][0]) + bi0) * v0
                  + tanh_fast(fmaf(cnt0, bb1, accm[j][1]) + bi1) * v1;
            acc1 += tanh_fast(fmaf(cnt1, bb0, accm[j][2]) + bi0) * v0
                  + tanh_fast(fmaf(cnt1, bb1, accm[j][3]) + bi1) * v1;
        }

        acc0 += __shfl_xor_sync(0xffffffffu, acc0, 1);
        acc0 += __shfl_xor_sync(0xffffffffu, acc0, 2);
        acc1 += __shfl_xor_sync(0xffffffffu, acc1, 1);
        acc1 += __shfl_xor_sync(0xffffffffu, acc1, 2);

        if (s_set > 0 && tig == 0) {
            sP[(s_set - 1) * 128 + wr * 16 + gid]     = acc0;
            sP[(s_set - 1) * 128 + wr * 16 + gid + 8] = acc1;
        }
        __syncthreads();

        if (s_set == 0 && tig == 0) {
            int i0 = wr * 16 + gid;
            acc0 += sP[i0] + sP[128 + i0] + sP[256 + i0];
            acc1 += sP[i0 + 8] + sP[128 + i0 + 8] + sP[256 + i0 + 8];
            int r0 = tile * K2_TILE + i0;
            {
                float z    = acc0 + c2s;
                float base = fmaxf(z, 0.f) + log1pf(expf(-fabsf(z)));
                float extm = sextc[i0] / fmaxf(cnt0, 1.f);
                g_v[r0]      = exp10f(log_k[r0]) * extm * base;
                g_rscale[r0] = 1.f;
            }
            int r1 = r0 + 8;
            {
                float z    = acc1 + c2s;
                float base = fmaxf(z, 0.f) + log1pf(expf(-fabsf(z)));
                float extm = sextc[i0 + 8] / fmaxf(cnt1, 1.f);
                g_v[r1]      = exp10f(log_k[r1]) * extm * base;
                g_rscale[r1] = 1.f;
            }
        }

        CP_WAIT0();
        __syncthreads();   // next buffer ready; sP consumed
        pb ^= 1;
    }
}

// ---------------- L6: total consumption per metabolite (edge-parallel) --------
__global__ void k_totcons(const int* __restrict__ met_sub,
                          const int* __restrict__ rxn_sub,
                          const float* __restrict__ sto_sub)
{
    int e = blockIdx.x * blockDim.x + threadIdx.x;
    if (e >= E_SUB) return;
    float c = sto_sub[e] * g_v[rxn_sub[e]] * DT;
    atomicAdd(&g_totcons[met_sub[e]], c);
}

// ---------------- L7: per-rxn min scale (edge-parallel atomicMin) -------------
__global__ void k_rscale(const float* __restrict__ x,
                         const int* __restrict__ met_sub,
                         const int* __restrict__ rxn_sub)
{
    int e = blockIdx.x * blockDim.x + threadIdx.x;
    if (e >= E_SUB) return;
    int   m    = met_sub[e];
    float tot  = g_totcons[m];
    float conc = x[m * 8 + 3];
    float sc   = (tot > 1e-12f) ? fminf(conc / tot, 1.0f) : 1.0f;
    atomicMin(reinterpret_cast<int*>(&g_rscale[rxn_sub[e]]), __float_as_int(sc));
}

// ---------------- L8: contributions + tail re-zero for next replay ------------
__global__ void k_contrib(const int* __restrict__ met_sub,
                          const int* __restrict__ rxn_sub,
                          const float* __restrict__ sto_sub,
                          const int* __restrict__ met_prod,
                          const int* __restrict__ rxn_prod,
                          const float* __restrict__ sto_prod,
                          float* __restrict__ out)
{
    int blk = blockIdx.x, tid = threadIdx.x;
    if (blk < CONTRIB_B) {
        int i = blk * 256 + tid;
        if (i >= E_SUB + E_PROD) return;
        int m, r; float sto;
        if (i < E_SUB) {
            m = met_sub[i];  r = rxn_sub[i];  sto = -sto_sub[i];
        } else {
            int e = i - E_SUB;
            m = met_prod[e]; r = rxn_prod[e]; sto = sto_prod[e];
        }
        atomicAdd(&out[m], sto * g_v[r] * g_rscale[r]);
    } else {
        // restore zero-state invariant for the next invocation
        int i = (blk - CONTRIB_B) * 256 + tid;
        int stride = (gridDim.x - CONTRIB_B) * 256;
        for (int p = i; p < N_RXN; p += stride) g_cnt[p] = 0;
        for (int p = i; p < NB1; p += stride) g_sstate[p] = 0ULL;
    }
}

// ---------------- launch ------------------------------------------------------
extern "C" void kernel_launch(void* const* d_in, const int* in_sizes, int n_in,
                              void* d_out, int out_size)
{
    const float* x        = (const float*)d_in[0];
    const int*   met_sub  = (const int*)  d_in[1];
    const int*   rxn_sub  = (const int*)  d_in[2];
    const float* sto_sub  = (const float*)d_in[3];
    const int*   met_prod = (const int*)  d_in[4];
    const int*   rxn_prod = (const int*)  d_in[5];
    const float* sto_prod = (const float*)d_in[6];
    const float* W1       = (const float*)d_in[7];
    const float* b1       = (const float*)d_in[8];
    const float* W2       = (const float*)d_in[9];
    const float* b2       = (const float*)d_in[10];
    const float* V1       = (const float*)d_in[11];
    const float* c1       = (const float*)d_in[12];
    const float* V2       = (const float*)d_in[13];
    const float* c2       = (const float*)d_in[14];
    const float* log_k    = (const float*)d_in[15];
    float* out = (float*)d_out;

    cudaFuncSetAttribute(k_gemm2, cudaFuncAttributeMaxDynamicSharedMemorySize,
                         G2_SMEM_BYTES);

    // 1: histogram + weight fold + zero(out, totcons)
    k_hist_init<<<HIST_B + HIDDEN + 1 + 256, 256>>>(rxn_sub, W2, V1, b2, out);
    // 2: single-pass scan -> g_start, g_cursor
    k_scan_lb<<<NB1, SCAN_BS>>>();
    // 3: CSR scatter
    k_scatter<<<(E_SUB + 255) / 256, 256>>>(rxn_sub);
    // 4: layer-1, warp-per-reaction (barrier-free)
    k_layer1<<<(N_RXN * 32 + 255) / 256, 256>>>(x, met_sub, sto_sub, W1, b1);
    // 5: dense GEMM + epilogue
    k_gemm2<<<K2_GRID, K2_THREADS, G2_SMEM_BYTES>>>(c1, V2, c2, log_k);
    // 6-8: limiting scale + output
    k_totcons<<<(E_SUB + 255) / 256, 256>>>(met_sub, rxn_sub, sto_sub);
    k_rscale<<<(E_SUB + 255) / 256, 256>>>(x, met_sub, rxn_sub);
    k_contrib<<<CONTRIB_B + 128, 256>>>(met_sub, rxn_sub, sto_sub,
                                        met_prod, rxn_prod, sto_prod, out);
}

// round 16
// speedup vs baseline: 1.2366x; 1.2366x over previous
#include <cuda_runtime.h>
#include <cuda_fp16.h>
#include <math.h>

#define N_MET   100000
#define N_RXN   200000
#define E_SUB   400000
#define E_PROD  400000
#define HIDDEN  128
#define MSG     64
#define DT      0.01f

#define SCAN_BS 512
#define NB1     ((N_RXN + SCAN_BS - 1) / SCAN_BS)   // 391

#define LDH 136     // smem stride (halves) for T and M tiles (conflict-free)
#define K2_TILE 64
#define K2_NTILES (N_RXN / K2_TILE)                 // 3125, exact
#define K2_GRID  296                                // 2 CTAs/SM, one wave
#define K2_THREADS 512
#define MAXE    256 // edge-staging chunk (per buffer)

#define HIST_B  ((E_SUB + 255) / 256)               // 1563

#define FT_GRID    296
#define FT_THREADS 256
#define FT_STRIDE  (FT_GRID * FT_THREADS)

// smem bytes: c1/V2/bb (1536) + cnt/ext (512) + P (1536) + E4 (8192)
//           + T half (64*LDH*2) + M half (128*LDH*2)
#define K2_SMEM_BYTES (1536 + 512 + 1536 + 2 * MAXE * 16 + K2_TILE * LDH * 2 + HIDDEN * LDH * 2)

// ---------------- scratch (device globals; no allocation allowed) -------------
// g_cnt, g_sstate, g_bar start zero (BSS). g_cnt/g_sstate are re-zeroed in the
// tail kernel, g_bar is re-zeroed by launch 1 of the SAME replay (first use is
// launch 5), so every invocation sees a consistent initial state.
__device__ int                g_cnt[N_RXN];
__device__ unsigned long long g_sstate[NB1];        // lookback scan state
__device__ unsigned           g_bar[2];             // grid-barrier counters
__device__ int                g_start[N_RXN];
__device__ int                g_cursor[N_RXN];
__device__ int                g_eidx[E_SUB];
__device__ __half             g_Mh[HIDDEN * HIDDEN];   // fp16 W2@V1, [n][k] layout
__device__ float              g_bb[HIDDEN];            // b2 @ V1
__device__ float              g_v[N_RXN];
__device__ float              g_rscale[N_RXN];
__device__ float              g_totcons[N_MET];

#define ST_AGG (1ULL << 62)
#define ST_PRE (2ULL << 62)
#define ST_VAL 0x3FFFFFFFFFFFFFFFULL

__device__ __forceinline__ float tanh_fast(float x) {
    float y; asm("tanh.approx.f32 %0, %1;" : "=f"(y) : "f"(x)); return y;
}
__device__ __forceinline__ unsigned smem_u32(const void* p) {
    return (unsigned)__cvta_generic_to_shared(p);
}
#define LDSM_X4(r0, r1, r2, r3, addr) \
    asm volatile("ldmatrix.sync.aligned.m8n8.x4.shared.b16 {%0,%1,%2,%3}, [%4];" \
                 : "=r"(r0), "=r"(r1), "=r"(r2), "=r"(r3) : "r"(addr))
#define LDSM_X2(r0, r1, addr) \
    asm volatile("ldmatrix.sync.aligned.m8n8.x2.shared.b16 {%0,%1}, [%2];" \
                 : "=r"(r0), "=r"(r1) : "r"(addr))

// software grid barrier: all FT_GRID blocks are co-resident by construction
__device__ __forceinline__ void gridbar(int which) {
    __syncthreads();
    __threadfence();
    if (threadIdx.x == 0) {
        unsigned v = atomicAdd(&g_bar[which], 1u) + 1u;
        if (v < FT_GRID)
            while (atomicAdd(&g_bar[which], 0u) < FT_GRID) { }
    }
    __syncthreads();
}

// ---------------- L1: histogram + weight folding + zeroing (fused) ------------
__global__ void k_hist_init(const int*   __restrict__ rxn_sub,
                            const float* __restrict__ W2,
                            const float* __restrict__ V1,
                            const float* __restrict__ b2,
                            float* __restrict__ out)
{
    int blk = blockIdx.x, tid = threadIdx.x;
    if (blk < HIST_B) {
        int e = blk * 256 + tid;
        if (e < E_SUB) atomicAdd(&g_cnt[rxn_sub[e]], 1);
    } else if (blk < HIST_B + HIDDEN) {
        if (tid < HIDDEN) {
            int j = blk - HIST_B;   // k-dim index
            float acc = 0.f;
            for (int k = 0; k < MSG; k++)
                acc = fmaf(W2[j * MSG + k], V1[k * HIDDEN + tid], acc);
            g_Mh[tid * HIDDEN + j] = __float2half_rn(acc);   // [n][k] (B col-major)
        }
    } else if (blk == HIST_B + HIDDEN) {
        if (tid < HIDDEN) {
            float acc = 0.f;
            for (int k = 0; k < MSG; k++)
                acc = fmaf(b2[k], V1[k * HIDDEN + tid], acc);
            g_bb[tid] = acc;
        }
    } else {
        if (blk == HIST_B + HIDDEN + 1 && tid == 0) {
            g_bar[0] = 0u;  // first use is launch 5 of this same replay
            g_bar[1] = 0u;
        }
        int i = (blk - (HIST_B + HIDDEN + 1)) * 256 + tid;
        int stride = (gridDim.x - (HIST_B + HIDDEN + 1)) * 256;
        for (int p = i; p < N_MET; p += stride) { g_totcons[p] = 0.f; out[p] = 0.f; }
    }
}

// ---------------- L2: single-pass decoupled-lookback exclusive scan -----------
__global__ void k_scan_lb() {
    __shared__ int s[SCAN_BS];
    __shared__ int s_running;
    int b = blockIdx.x, t = threadIdx.x;
    int i = b * SCAN_BS + t;
    int v = (i < N_RXN) ? g_cnt[i] : 0;
    s[t] = v; __syncthreads();
    for (int off = 1; off < SCAN_BS; off <<= 1) {
        int xx = (t >= off) ? s[t - off] : 0;
        __syncthreads();
        s[t] += xx;
        __syncthreads();
    }
    if (t == 0) {
        unsigned long long total = (unsigned long long)s[SCAN_BS - 1];
        if (b == 0) {
            atomicExch(&g_sstate[0], ST_PRE | total);
            s_running = 0;
        } else {
            atomicExch(&g_sstate[b], ST_AGG | total);
            unsigned long long run = 0;
            for (int pb = b - 1; pb >= 0; pb--) {
                unsigned long long st;
                do { st = atomicAdd(&g_sstate[pb], 0ULL); } while ((st >> 62) == 0ULL);
                run += st & ST_VAL;
                if ((st >> 62) == 2ULL) break;
            }
            atomicExch(&g_sstate[b], ST_PRE | (run + total));
            s_running = (int)run;
        }
    }
    __syncthreads();
    if (i < N_RXN) {
        int st = s_running + s[t] - v;
        g_start[i]  = st;
        g_cursor[i] = st;
    }
}

// ---------------- L3: scatter edge ids into CSR order -------------------------
__global__ void k_scatter(const int* __restrict__ rxn_sub) {
    int e = blockIdx.x * blockDim.x + threadIdx.x;
    if (e >= E_SUB) return;
    int pos = atomicAdd(&g_cursor[rxn_sub[e]], 1);
    g_eidx[pos] = e;
}

// ---------------- L4: persistent gather + layer1 + fp16 GEMM (R14 form) -------
__global__ __launch_bounds__(K2_THREADS, 2)
void k2_gemm(const float* __restrict__ x,
             const int*   __restrict__ met_sub,
             const float* __restrict__ sto_sub,
             const float* __restrict__ W1,
             const float* __restrict__ b1,
             const float* __restrict__ c1v,
             const float* __restrict__ V2,
             const float* __restrict__ c2,
             const float* __restrict__ log_k)
{
    extern __shared__ float sm[];
    float*    sc1  = sm;                               // 128
    float*    sV2  = sc1 + 128;                        // 128
    float*    sbb  = sV2 + 128;                        // 128
    float*    scnt = sbb + 128;                        // 64
    float*    sext = scnt + 64;                        // 64
    float*    sP   = sext + 64;                        // 384 (3 partial sets)
    float4*   sE4  = (float4*)(sP + 384);              // 2 x MAXE float4
    __half*   sTh  = (__half*)(sE4 + 2 * MAXE);        // 64 x LDH halves
    __half*   sMh  = sTh + K2_TILE * LDH;              // 128 x LDH halves

    int tid = threadIdx.x;
    int w = tid >> 5, lane = tid & 31, gid = lane >> 2, tig = lane & 3;
    int wr = w & 3;                                    // row-group for mma
    int s_set = w >> 2;                                // nt quarter 0..3
    int nt0 = s_set * 4;

    // stage weights & biases ONCE per block
    if (tid < 128) {
        sc1[tid] = c1v[tid];
        sV2[tid] = V2[tid];
        sbb[tid] = g_bb[tid];
    }
    for (int i = tid; i < HIDDEN * HIDDEN / 2; i += K2_THREADS) {
        int row = i >> 6, col2 = i & 63;               // 64 half2 per row
        reinterpret_cast<__half2*>(sMh)[row * (LDH / 2) + col2] =
            reinterpret_cast<const __half2*>(g_Mh)[i];
    }
    float c2s = c2[0];

    // per-lane register weights: units 4*lane .. 4*lane+3
    float4 u4 = reinterpret_cast<const float4*>(W1)[lane];
    float4 w4 = reinterpret_cast<const float4*>(W1 + HIDDEN)[lane];
    float4 b4 = reinterpret_cast<const float4*>(b1)[lane];

    // ldmatrix base addresses (constant across tiles)
    unsigned aaddr = smem_u32(sTh) +
        (((wr * 16 + (lane & 15)) * LDH + 8 * (lane >> 4)) << 1);
    unsigned baddr[4];
    #pragma unroll
    for (int j = 0; j < 4; j++)
        baddr[j] = smem_u32(sMh) +
            ((((nt0 + j) * 8 + (lane & 7)) * LDH + 8 * ((lane >> 3) & 1)) << 1);

    // prologue: stage first tile's edges into buffer 0
    int pb = 0;
    {
        int rf = blockIdx.x * K2_TILE;
        int eb = g_start[rf];
        int te = g_start[rf + K2_TILE - 1] + g_cnt[rf + K2_TILE - 1] - eb;
        int ch = min(te, MAXE);
        for (int i = tid; i < ch; i += K2_THREADS) {
            int idx = g_eidx[eb + i];
            int met = met_sub[idx];
            sE4[i] = make_float4(x[met * 8 + 3], sto_sub[idx], x[met * 8 + 4], 0.f);
        }
    }

    for (int tile = blockIdx.x; tile < K2_NTILES; tile += K2_GRID) {
        int r_first = tile * K2_TILE;
        int e_begin = g_start[r_first];
        int last    = r_first + K2_TILE - 1;
        int totE    = g_start[last] + g_cnt[last] - e_begin;

        int rb = r_first + 4 * w;
        int s0 = g_start[rb + 0] - e_begin, c0 = g_cnt[rb + 0];
        int s1 = g_start[rb + 1] - e_begin, c1 = g_cnt[rb + 1];
        int s2 = g_start[rb + 2] - e_begin, c2n = g_cnt[rb + 2];
        int s3 = g_start[rb + 3] - e_begin, c3 = g_cnt[rb + 3];

        float4* sEcur = sE4 + pb * MAXE;

        float acc00=0.f,acc01=0.f,acc02=0.f,acc03=0.f;
        float acc10=0.f,acc11=0.f,acc12=0.f,acc13=0.f;
        float acc20=0.f,acc21=0.f,acc22=0.f,acc23=0.f;
        float acc30=0.f,acc31=0.f,acc32=0.f,acc33=0.f;
        float ext0=0.f, ext1=0.f, ext2=0.f, ext3=0.f;

        __syncthreads();   // prefetched sE ready; sT/sP from prev tile released

        for (int base = 0; base < totE; base += MAXE) {
            int ch = min(MAXE, totE - base);
            if (base > 0) {   // rare slow path: restage into own buffer
                __syncthreads();
                for (int i = tid; i < ch; i += K2_THREADS) {
                    int idx = g_eidx[e_begin + base + i];
                    int met = met_sub[idx];
                    sEcur[i] = make_float4(x[met * 8 + 3], sto_sub[idx], x[met * 8 + 4], 0.f);
                }
                __syncthreads();
            }
            #define ROW_LOOP(RR, SR, CN) { \
                int lo = max(SR, base), hi = min(SR + CN, base + ch); \
                for (int l = lo; l < hi; l++) { \
                    float4 e = sEcur[l - base]; \
                    ext##RR += e.z; \
                    acc##RR##0 += tanh_fast(fmaf(e.x, u4.x, fmaf(e.y, w4.x, b4.x))); \
                    acc##RR##1 += tanh_fast(fmaf(e.x, u4.y, fmaf(e.y, w4.y, b4.y))); \
                    acc##RR##2 += tanh_fast(fmaf(e.x, u4.z, fmaf(e.y, w4.z, b4.z))); \
                    acc##RR##3 += tanh_fast(fmaf(e.x, u4.w, fmaf(e.y, w4.w, b4.w))); \
                } }
            ROW_LOOP(0, s0, c0)
            ROW_LOOP(1, s1, c1)
            ROW_LOOP(2, s2, c2n)
            ROW_LOOP(3, s3, c3)
            #undef ROW_LOOP
        }

        #define ST_ROW(RR) { \
            __half2 h0 = __floats2half2_rn(acc##RR##0, acc##RR##1); \
            __half2 h1 = __floats2half2_rn(acc##RR##2, acc##RR##3); \
            *reinterpret_cast<__half2*>(&sTh[(4 * w + RR) * LDH + 4 * lane])     = h0; \
            *reinterpret_cast<__half2*>(&sTh[(4 * w + RR) * LDH + 4 * lane + 2]) = h1; }
        ST_ROW(0) ST_ROW(1) ST_ROW(2) ST_ROW(3)
        #undef ST_ROW
        if (lane == 0) {
            scnt[4 * w + 0] = (float)c0;  sext[4 * w + 0] = ext0;
            scnt[4 * w + 1] = (float)c1;  sext[4 * w + 1] = ext1;
            scnt[4 * w + 2] = (float)c2n; sext[4 * w + 2] = ext2;
            scnt[4 * w + 3] = (float)c3;  sext[4 * w + 3] = ext3;
        }
        __syncthreads();

        // prefetch next tile's edges into alternate buffer (overlaps with mma)
        int tnext = tile + K2_GRID;
        if (tnext < K2_NTILES) {
            float4* sEnx = sE4 + (pb ^ 1) * MAXE;
            int rf2 = tnext * K2_TILE;
            int eb2 = g_start[rf2];
            int te2 = g_start[rf2 + K2_TILE - 1] + g_cnt[rf2 + K2_TILE - 1] - eb2;
            int ch2 = min(te2, MAXE);
            for (int i = tid; i < ch2; i += K2_THREADS) {
                int idx = g_eidx[eb2 + i];
                int met = met_sub[idx];
                sEnx[i] = make_float4(x[met * 8 + 3], sto_sub[idx], x[met * 8 + 4], 0.f);
            }
        }

        // ---- mma: fp16 m16n8k16, ldmatrix operands, 4 nt-tiles per warp ----
        float accm[4][4];
        #pragma unroll
        for (int j = 0; j < 4; j++) {
            accm[j][0] = 0.f; accm[j][1] = 0.f; accm[j][2] = 0.f; accm[j][3] = 0.f;
        }

        #pragma unroll
        for (int kt = 0; kt < 8; kt++) {
            unsigned koff = kt * 32;                   // 16 halves = 32 bytes
            unsigned a0, a1, a2, a3;
            LDSM_X4(a0, a1, a2, a3, aaddr + koff);
            #pragma unroll
            for (int j = 0; j < 4; j++) {
                unsigned b0, b1;
                LDSM_X2(b0, b1, baddr[j] + koff);
                asm volatile(
                    "mma.sync.aligned.m16n8k16.row.col.f32.f16.f16.f32 "
                    "{%0,%1,%2,%3}, {%4,%5,%6,%7}, {%8,%9}, {%0,%1,%2,%3};"
                    : "+f"(accm[j][0]), "+f"(accm[j][1]), "+f"(accm[j][2]), "+f"(accm[j][3])
                    : "r"(a0), "r"(a1), "r"(a2), "r"(a3), "r"(b0), "r"(b1));
            }
        }

        float cnt0 = scnt[wr * 16 + gid], cnt1 = scnt[wr * 16 + gid + 8];
        float acc0 = 0.f, acc1 = 0.f;
        #pragma unroll
        for (int j = 0; j < 4; j++) {
            int n0 = (nt0 + j) * 8;
            int col0 = n0 + 2 * tig, col1 = col0 + 1;
            float bi0 = sc1[col0], bi1 = sc1[col1];
            float bb0 = sbb[col0], bb1 = sbb[col1];
            float v0  = sV2[col0], v1  = sV2[col1];
            acc0 += tanh_fast(fmaf(cnt0, bb0, accm[j][0]) + bi0) * v0
                  + tanh_fast(fmaf(cnt0, bb1, accm[j][1]) + bi1) * v1;
            acc1 += tanh_fast(fmaf(cnt1, bb0, accm[j][2]) + bi0) * v0
                  + tanh_fast(fmaf(cnt1, bb1, accm[j][3]) + bi1) * v1;
        }

        acc0 += __shfl_xor_sync(0xffffffffu, acc0, 1);
        acc0 += __shfl_xor_sync(0xffffffffu, acc0, 2);
        acc1 += __shfl_xor_sync(0xffffffffu, acc1, 1);
        acc1 += __shfl_xor_sync(0xffffffffu, acc1, 2);

        if (s_set > 0 && tig == 0) {
            sP[(s_set - 1) * 128 + wr * 16 + gid]     = acc0;
            sP[(s_set - 1) * 128 + wr * 16 + gid + 8] = acc1;
        }
        __syncthreads();

        if (s_set == 0 && tig == 0) {
            int i0 = wr * 16 + gid;
            acc0 += sP[i0] + sP[128 + i0] + sP[256 + i0];
            acc1 += sP[i0 + 8] + sP[128 + i0 + 8] + sP[256 + i0 + 8];
            int r0 = r_first + i0;
            {
                float z    = acc0 + c2s;
                float base = fmaxf(z, 0.f) + log1pf(expf(-fabsf(z)));
                float extm = sext[i0] / fmaxf(scnt[i0], 1.f);
                g_v[r0]      = exp10f(log_k[r0]) * extm * base;
                g_rscale[r0] = 1.f;
            }
            int r1 = r0 + 8;
            {
                float z    = acc1 + c2s;
                float base = fmaxf(z, 0.f) + log1pf(expf(-fabsf(z)));
                float extm = sext[i0 + 8] / fmaxf(scnt[i0 + 8], 1.f);
                g_v[r1]      = exp10f(log_k[r1]) * extm * base;
                g_rscale[r1] = 1.f;
            }
        }

        pb ^= 1;
    }
}

// ---------------- L5: fused tail — totcons / rscale / contrib + re-zero -------
// Persistent 296 blocks, all co-resident; two software grid barriers between
// the three edge-parallel phases. Index arrays stay L1-resident across phases.
__global__ __launch_bounds__(FT_THREADS)
void k_tail(const float* __restrict__ x,
            const int*   __restrict__ met_sub,
            const int*   __restrict__ rxn_sub,
            const float* __restrict__ sto_sub,
            const int*   __restrict__ met_prod,
            const int*   __restrict__ rxn_prod,
            const float* __restrict__ sto_prod,
            float* __restrict__ out)
{
    int t0 = blockIdx.x * FT_THREADS + threadIdx.x;

    // phase A: total consumption per metabolite
    for (int e = t0; e < E_SUB; e += FT_STRIDE) {
        float c = sto_sub[e] * g_v[rxn_sub[e]] * DT;
        atomicAdd(&g_totcons[met_sub[e]], c);
    }
    gridbar(0);

    // phase B: per-rxn min scale
    for (int e = t0; e < E_SUB; e += FT_STRIDE) {
        int   m    = met_sub[e];
        float tot  = g_totcons[m];
        float conc = x[m * 8 + 3];
        float sc   = (tot > 1e-12f) ? fminf(conc / tot, 1.0f) : 1.0f;
        atomicMin(reinterpret_cast<int*>(&g_rscale[rxn_sub[e]]), __float_as_int(sc));
    }
    gridbar(1);

    // phase C: signed contributions + restore zero-state for next replay
    for (int i = t0; i < E_SUB + E_PROD; i += FT_STRIDE) {
        int m, r; float sto;
        if (i < E_SUB) {
            m = met_sub[i];  r = rxn_sub[i];  sto = -sto_sub[i];
        } else {
            int e = i - E_SUB;
            m = met_prod[e]; r = rxn_prod[e]; sto = sto_prod[e];
        }
        atomicAdd(&out[m], sto * g_v[r] * g_rscale[r]);
    }
    for (int p = t0; p < N_RXN; p += FT_STRIDE) g_cnt[p] = 0;
    for (int p = t0; p < NB1; p += FT_STRIDE) g_sstate[p] = 0ULL;
}

// ---------------- launch ------------------------------------------------------
extern "C" void kernel_launch(void* const* d_in, const int* in_sizes, int n_in,
                              void* d_out, int out_size)
{
    const float* x        = (const float*)d_in[0];
    const int*   met_sub  = (const int*)  d_in[1];
    const int*   rxn_sub  = (const int*)  d_in[2];
    const float* sto_sub  = (const float*)d_in[3];
    const int*   met_prod = (const int*)  d_in[4];
    const int*   rxn_prod = (const int*)  d_in[5];
    const float* sto_prod = (const float*)d_in[6];
    const float* W1       = (const float*)d_in[7];
    const float* b1       = (const float*)d_in[8];
    const float* W2       = (const float*)d_in[9];
    const float* b2       = (const float*)d_in[10];
    const float* V1       = (const float*)d_in[11];
    const float* c1       = (const float*)d_in[12];
    const float* V2       = (const float*)d_in[13];
    const float* c2       = (const float*)d_in[14];
    const float* log_k    = (const float*)d_in[15];
    float* out = (float*)d_out;

    cudaFuncSetAttribute(k2_gemm, cudaFuncAttributeMaxDynamicSharedMemorySize,
                         K2_SMEM_BYTES);

    // 1: histogram + weight fold + zero(out, totcons, barriers)
    k_hist_init<<<HIST_B + HIDDEN + 1 + 256, 256>>>(rxn_sub, W2, V1, b2, out);
    // 2: single-pass scan -> g_start, g_cursor
    k_scan_lb<<<NB1, SCAN_BS>>>();
    // 3: CSR scatter
    k_scatter<<<(E_SUB + 255) / 256, 256>>>(rxn_sub);
    // 4: the big fused kernel (profiled slot)
    k2_gemm<<<K2_GRID, K2_THREADS, K2_SMEM_BYTES>>>(x, met_sub, sto_sub,
                                                    W1, b1, c1, V2, c2, log_k);
    // 5: fused tail (totcons -> rscale -> contrib) with grid barriers
    k_tail<<<FT_GRID, FT_THREADS>>>(x, met_sub, rxn_sub, sto_sub,
                                    met_prod, rxn_prod, sto_prod, out);
}

// round 17
// speedup vs baseline: 1.3232x; 1.0700x over previous
#include <cuda_runtime.h>
#include <cuda_fp16.h>
#include <math.h>

#define N_MET   100000
#define N_RXN   200000
#define E_SUB   400000
#define E_PROD  400000
#define HIDDEN  128
#define MSG     64
#define DT      0.01f

#define SCAN_BS 512
#define NB1     ((N_RXN + SCAN_BS - 1) / SCAN_BS)   // 391

#define LDH 136
#define K2_TILE 64
#define K2_NTILES (N_RXN / K2_TILE)                 // 3125
#define K2_GRID  296                                // 2 CTAs/SM
#define K2_THREADS 512
#define MAXE    256

#define HIST_B    ((E_SUB + 255) / 256)             // 1563
#define CONTRIB_B ((E_SUB + E_PROD + 255) / 256)    // 3125

// smem bytes: c1/V2/bb (1536) + scnt/sext double (1024) + sP (512) + E4 (8192)
//           + T double (2*64*LDH*2) + M (128*LDH*2)
#define K2_SMEM_BYTES (1536 + 1024 + 512 + 2 * MAXE * 16 + 2 * K2_TILE * LDH * 2 + HIDDEN * LDH * 2)

// named barrier ids
#define BAR_FULL0  1
#define BAR_FULL1  2
#define BAR_EMPTY0 3
#define BAR_EMPTY1 4
#define BAR_PROD   5
#define BAR_CONS   6

// ---------------- scratch -----------------------------------------------------
__device__ int                g_cnt[N_RXN];
__device__ unsigned long long g_sstate[NB1];
__device__ int                g_start[N_RXN];
__device__ int                g_cursor[N_RXN];
__device__ int                g_eidx[E_SUB];
__device__ __half             g_Mh[HIDDEN * HIDDEN];
__device__ float              g_bb[HIDDEN];
__device__ float              g_v[N_RXN];
__device__ float              g_rscale[N_RXN];
__device__ float              g_totcons[N_MET];

#define ST_AGG (1ULL << 62)
#define ST_PRE (2ULL << 62)
#define ST_VAL 0x3FFFFFFFFFFFFFFFULL

__device__ __forceinline__ float tanh_fast(float x) {
    float y; asm("tanh.approx.f32 %0, %1;" : "=f"(y) : "f"(x)); return y;
}
__device__ __forceinline__ unsigned smem_u32(const void* p) {
    return (unsigned)__cvta_generic_to_shared(p);
}
#define LDSM_X4(r0, r1, r2, r3, addr) \
    asm volatile("ldmatrix.sync.aligned.m8n8.x4.shared.b16 {%0,%1,%2,%3}, [%4];" \
                 : "=r"(r0), "=r"(r1), "=r"(r2), "=r"(r3) : "r"(addr))
#define BSYNC(id, cnt)   asm volatile("bar.sync %0, %1;"   :: "r"(id), "r"(cnt) : "memory")
#define BARRIVE(id, cnt) asm volatile("bar.arrive %0, %1;" :: "r"(id), "r"(cnt) : "memory")

// ---------------- L1: histogram + weight folding + zeroing --------------------
__global__ void k_hist_init(const int*   __restrict__ rxn_sub,
                            const float* __restrict__ W2,
                            const float* __restrict__ V1,
                            const float* __restrict__ b2,
                            float* __restrict__ out)
{
    int blk = blockIdx.x, tid = threadIdx.x;
    if (blk < HIST_B) {
        int e = blk * 256 + tid;
        if (e < E_SUB) atomicAdd(&g_cnt[rxn_sub[e]], 1);
    } else if (blk < HIST_B + HIDDEN) {
        if (tid < HIDDEN) {
            int j = blk - HIST_B;
            float acc = 0.f;
            for (int k = 0; k < MSG; k++)
                acc = fmaf(W2[j * MSG + k], V1[k * HIDDEN + tid], acc);
            g_Mh[tid * HIDDEN + j] = __float2half_rn(acc);
        }
    } else if (blk == HIST_B + HIDDEN) {
        if (tid < HIDDEN) {
            float acc = 0.f;
            for (int k = 0; k < MSG; k++)
                acc = fmaf(b2[k], V1[k * HIDDEN + tid], acc);
            g_bb[tid] = acc;
        }
    } else {
        int i = (blk - (HIST_B + HIDDEN + 1)) * 256 + tid;
        int stride = (gridDim.x - (HIST_B + HIDDEN + 1)) * 256;
        for (int p = i; p < N_MET; p += stride) { g_totcons[p] = 0.f; out[p] = 0.f; }
    }
}

// ---------------- L2: single-pass decoupled-lookback exclusive scan -----------
__global__ void k_scan_lb() {
    __shared__ int s[SCAN_BS];
    __shared__ int s_running;
    int b = blockIdx.x, t = threadIdx.x;
    int i = b * SCAN_BS + t;
    int v = (i < N_RXN) ? g_cnt[i] : 0;
    s[t] = v; __syncthreads();
    for (int off = 1; off < SCAN_BS; off <<= 1) {
        int xx = (t >= off) ? s[t - off] : 0;
        __syncthreads();
        s[t] += xx;
        __syncthreads();
    }
    if (t == 0) {
        unsigned long long total = (unsigned long long)s[SCAN_BS - 1];
        if (b == 0) {
            atomicExch(&g_sstate[0], ST_PRE | total);
            s_running = 0;
        } else {
            atomicExch(&g_sstate[b], ST_AGG | total);
            unsigned long long run = 0;
            for (int pb = b - 1; pb >= 0; pb--) {
                unsigned long long st;
                do { st = atomicAdd(&g_sstate[pb], 0ULL); } while ((st >> 62) == 0ULL);
                run += st & ST_VAL;
                if ((st >> 62) == 2ULL) break;
            }
            atomicExch(&g_sstate[b], ST_PRE | (run + total));
            s_running = (int)run;
        }
    }
    __syncthreads();
    if (i < N_RXN) {
        int st = s_running + s[t] - v;
        g_start[i]  = st;
        g_cursor[i] = st;
    }
}

// ---------------- L3: scatter edge ids into CSR order -------------------------
__global__ void k_scatter(const int* __restrict__ rxn_sub) {
    int e = blockIdx.x * blockDim.x + threadIdx.x;
    if (e >= E_SUB) return;
    int pos = atomicAdd(&g_cursor[rxn_sub[e]], 1);
    g_eidx[pos] = e;
}

// ---------------- L4: warp-specialized producer/consumer GEMM -----------------
// threads 0-255: producers (staging + layer-1 -> sT double buffer)
// threads 256-511: consumers (ldmatrix + HMMA + epilogue)
__global__ __launch_bounds__(K2_THREADS, 2)
void k2_gemm(const float* __restrict__ x,
             const int*   __restrict__ met_sub,
             const float* __restrict__ sto_sub,
             const float* __restrict__ W1,
             const float* __restrict__ b1,
             const float* __restrict__ c1v,
             const float* __restrict__ V2,
             const float* __restrict__ c2,
             const float* __restrict__ log_k)
{
    extern __shared__ float sm[];
    float*    sc1  = sm;                               // 128
    float*    sV2  = sc1 + 128;                        // 128
    float*    sbb  = sV2 + 128;                        // 128
    float*    scnt = sbb + 128;                        // 2 x 64
    float*    sext = scnt + 128;                       // 2 x 64
    float*    sP   = sext + 128;                       // 128
    float4*   sE4  = (float4*)(sP + 128);              // 2 x MAXE float4
    __half*   sTh  = (__half*)(sE4 + 2 * MAXE);        // 2 x 64 x LDH halves
    __half*   sMh  = sTh + 2 * K2_TILE * LDH;          // 128 x LDH halves

    int tid = threadIdx.x;
    int lane = tid & 31;

    if (tid < 128) {
        sc1[tid] = c1v[tid];
        sV2[tid] = V2[tid];
        sbb[tid] = g_bb[tid];
    }
    for (int i = tid; i < HIDDEN * HIDDEN / 2; i += K2_THREADS) {
        int row = i >> 6, col2 = i & 63;
        reinterpret_cast<__half2*>(sMh)[row * (LDH / 2) + col2] =
            reinterpret_cast<const __half2*>(g_Mh)[i];
    }
    __syncthreads();

    if (tid < 256) {
        // ======================= PRODUCERS =======================
        int pw = tid >> 5;   // 0..7, rows 8*pw .. 8*pw+7
        float4 u4 = reinterpret_cast<const float4*>(W1)[lane];
        float4 w4 = reinterpret_cast<const float4*>(W1 + HIDDEN)[lane];
        float4 b4 = reinterpret_cast<const float4*>(b1)[lane];

        // prologue: stage first tile's edges into sE buffer 0
        int cur = 0, pb = 0;
        {
            int rf = blockIdx.x * K2_TILE;
            int eb = g_start[rf];
            int te = g_start[rf + K2_TILE - 1] + g_cnt[rf + K2_TILE - 1] - eb;
            int ch = min(te, MAXE);
            for (int i = tid; i < ch; i += 256) {
                int idx = g_eidx[eb + i];
                int met = met_sub[idx];
                sE4[i] = make_float4(x[met * 8 + 3], sto_sub[idx], x[met * 8 + 4], 0.f);
            }
            BSYNC(BAR_PROD, 256);
        }

        for (int tile = blockIdx.x; tile < K2_NTILES; tile += K2_GRID) {
            int r_first = tile * K2_TILE;
            int e_begin = g_start[r_first];
            int last    = r_first + K2_TILE - 1;
            int totE    = g_start[last] + g_cnt[last] - e_begin;
            bool fast   = (totE <= MAXE);
            float4* sEcur = sE4 + cur * MAXE;

            BSYNC(pb ? BAR_EMPTY1 : BAR_EMPTY0, 512);  // consumers done with sT[pb]

            __half* sTp  = sTh + pb * K2_TILE * LDH;
            float*  scp  = scnt + pb * 64;
            float*  sep  = sext + pb * 64;

            #pragma unroll 2
            for (int r8 = 0; r8 < 8; r8++) {
                int row = 8 * pw + r8;
                int gr  = r_first + row;
                int s   = g_start[gr] - e_begin;
                int c   = g_cnt[gr];
                float a0 = 0.f, a1 = 0.f, a2 = 0.f, a3 = 0.f, ext = 0.f;
                if (fast) {
                    for (int l = s; l < s + c; l++) {
                        float4 e = sEcur[l];
                        ext += e.z;
                        a0 += tanh_fast(fmaf(e.x, u4.x, fmaf(e.y, w4.x, b4.x)));
                        a1 += tanh_fast(fmaf(e.x, u4.y, fmaf(e.y, w4.y, b4.y)));
                        a2 += tanh_fast(fmaf(e.x, u4.z, fmaf(e.y, w4.z, b4.z)));
                        a3 += tanh_fast(fmaf(e.x, u4.w, fmaf(e.y, w4.w, b4.w)));
                    }
                } else {
                    for (int l = 0; l < c; l++) {
                        int   idx = g_eidx[e_begin + s + l];
                        int   met = met_sub[idx];
                        float av  = x[met * 8 + 3];
                        float st  = sto_sub[idx];
                        ext += x[met * 8 + 4];
                        a0 += tanh_fast(fmaf(av, u4.x, fmaf(st, w4.x, b4.x)));
                        a1 += tanh_fast(fmaf(av, u4.y, fmaf(st, w4.y, b4.y)));
                        a2 += tanh_fast(fmaf(av, u4.z, fmaf(st, w4.z, b4.z)));
                        a3 += tanh_fast(fmaf(av, u4.w, fmaf(st, w4.w, b4.w)));
                    }
                }
                __half2 h0 = __floats2half2_rn(a0, a1);
                __half2 h1 = __floats2half2_rn(a2, a3);
                float2 pk = make_float2(__uint_as_float(*(unsigned*)&h0),
                                        __uint_as_float(*(unsigned*)&h1));
                *reinterpret_cast<float2*>(&sTp[row * LDH + 4 * lane]) = pk;
                if (lane == 0) { scp[row] = (float)c; sep[row] = ext; }
            }

            BARRIVE(pb ? BAR_FULL1 : BAR_FULL0, 512);  // sT[pb] ready

            // prefetch next tile's edges into alternate sE buffer
            int tnext = tile + K2_GRID;
            if (tnext < K2_NTILES) {
                float4* sEnx = sE4 + (cur ^ 1) * MAXE;
                int rf2 = tnext * K2_TILE;
                int eb2 = g_start[rf2];
                int te2 = g_start[rf2 + K2_TILE - 1] + g_cnt[rf2 + K2_TILE - 1] - eb2;
                int ch2 = min(te2, MAXE);
                for (int i = tid; i < ch2; i += 256) {
                    int idx = g_eidx[eb2 + i];
                    int met = met_sub[idx];
                    sE4[(cur ^ 1) * MAXE + 0] = sE4[(cur ^ 1) * MAXE + 0]; // no-op safety
                    sEnx[i] = make_float4(x[met * 8 + 3], sto_sub[idx], x[met * 8 + 4], 0.f);
                }
            }
            BSYNC(BAR_PROD, 256);
            cur ^= 1; pb ^= 1;
        }
    } else {
        // ======================= CONSUMERS =======================
        int cw = (tid - 256) >> 5;     // 0..7
        int wr = cw & 3;               // row-group
        int half = cw >> 2;            // nt half: j base = half*8
        int nt0 = half * 8;
        int gid = lane >> 2, tig = lane & 3;
        float c2s = c2[0];

        // pre-arm EMPTY for both buffers
        BARRIVE(BAR_EMPTY0, 512);
        BARRIVE(BAR_EMPTY1, 512);

        // A-frag addresses for both T buffers
        unsigned aoff = (((wr * 16 + (lane & 15)) * LDH + 8 * (lane >> 4)) << 1);
        unsigned abase0 = smem_u32(sTh) + aoff;
        unsigned abase1 = smem_u32(sTh + K2_TILE * LDH) + aoff;

        // B x4 addresses: quad q covers j = nt0+2q, nt0+2q+1
        unsigned baddr4[4];
        #pragma unroll
        for (int q = 0; q < 4; q++) {
            int jj = nt0 + 2 * q + ((lane >> 4) & 1);        // lane groups 16-31 -> j+1
            int kh = 8 * ((lane >> 3) & 1);                  // groups 8-15 / 24-31 -> k-high
            baddr4[q] = smem_u32(sMh) + (((jj * 8 + (lane & 7)) * LDH + kh) << 1);
        }

        int pb = 0;
        for (int tile = blockIdx.x; tile < K2_NTILES; tile += K2_GRID) {
            BSYNC(pb ? BAR_FULL1 : BAR_FULL0, 512);   // sT[pb] ready

            unsigned abase = pb ? abase1 : abase0;
            float* scp = scnt + pb * 64;
            float* sep = sext + pb * 64;
            float cnt0 = scp[wr * 16 + gid], cnt1 = scp[wr * 16 + gid + 8];

            float acc0 = 0.f, acc1 = 0.f;
            #pragma unroll
            for (int ip = 0; ip < 2; ip++) {
                float accm[4][4];
                #pragma unroll
                for (int j = 0; j < 4; j++) {
                    accm[j][0] = 0.f; accm[j][1] = 0.f; accm[j][2] = 0.f; accm[j][3] = 0.f;
                }
                #pragma unroll
                for (int kt = 0; kt < 8; kt++) {
                    unsigned koff = kt * 32;
                    unsigned a0, a1, a2, a3;
                    LDSM_X4(a0, a1, a2, a3, abase + koff);
                    #pragma unroll
                    for (int jp = 0; jp < 2; jp++) {
                        unsigned b0, b1, b2, b3;
                        LDSM_X4(b0, b1, b2, b3, baddr4[ip * 2 + jp] + koff);
                        asm volatile(
                            "mma.sync.aligned.m16n8k16.row.col.f32.f16.f16.f32 "
                            "{%0,%1,%2,%3}, {%4,%5,%6,%7}, {%8,%9}, {%0,%1,%2,%3};"
                            : "+f"(accm[jp*2][0]), "+f"(accm[jp*2][1]),
                              "+f"(accm[jp*2][2]), "+f"(accm[jp*2][3])
                            : "r"(a0), "r"(a1), "r"(a2), "r"(a3), "r"(b0), "r"(b1));
                        asm volatile(
                            "mma.sync.aligned.m16n8k16.row.col.f32.f16.f16.f32 "
                            "{%0,%1,%2,%3}, {%4,%5,%6,%7}, {%8,%9}, {%0,%1,%2,%3};"
                            : "+f"(accm[jp*2+1][0]), "+f"(accm[jp*2+1][1]),
                              "+f"(accm[jp*2+1][2]), "+f"(accm[jp*2+1][3])
                            : "r"(a0), "r"(a1), "r"(a2), "r"(a3), "r"(b2), "r"(b3));
                    }
                }
                #pragma unroll
                for (int j = 0; j < 4; j++) {
                    int n0 = (nt0 + ip * 4 + j) * 8;
                    int col0 = n0 + 2 * tig, col1 = col0 + 1;
                    float bi0 = sc1[col0], bi1 = sc1[col1];
                    float bb0 = sbb[col0], bb1 = sbb[col1];
                    float v0  = sV2[col0], v1  = sV2[col1];
                    acc0 += tanh_fast(fmaf(cnt0, bb0, accm[j][0]) + bi0) * v0
                          + tanh_fast(fmaf(cnt0, bb1, accm[j][1]) + bi1) * v1;
                    acc1 += tanh_fast(fmaf(cnt1, bb0, accm[j][2]) + bi0) * v0
                          + tanh_fast(fmaf(cnt1, bb1, accm[j][3]) + bi1) * v1;
                }
            }

            acc0 += __shfl_xor_sync(0xffffffffu, acc0, 1);
            acc0 += __shfl_xor_sync(0xffffffffu, acc0, 2);
            acc1 += __shfl_xor_sync(0xffffffffu, acc1, 1);
            acc1 += __shfl_xor_sync(0xffffffffu, acc1, 2);

            if (half == 1 && tig == 0) {
                sP[wr * 16 + gid]     = acc0;
                sP[wr * 16 + gid + 8] = acc1;
            }
            BSYNC(BAR_CONS, 256);

            if (half == 0 && tig == 0) {
                int i0 = wr * 16 + gid;
                acc0 += sP[i0];
                acc1 += sP[i0 + 8];
                int r0 = tile * K2_TILE + i0;
                {
                    float z    = acc0 + c2s;
                    float base = fmaxf(z, 0.f) + log1pf(expf(-fabsf(z)));
                    float extm = sep[i0] / fmaxf(cnt0, 1.f);
                    g_v[r0]      = exp10f(log_k[r0]) * extm * base;
                    g_rscale[r0] = 1.f;
                }
                int r1 = r0 + 8;
                {
                    float z    = acc1 + c2s;
                    float base = fmaxf(z, 0.f) + log1pf(expf(-fabsf(z)));
                    float extm = sep[i0 + 8] / fmaxf(cnt1, 1.f);
                    g_v[r1]      = exp10f(log_k[r1]) * extm * base;
                    g_rscale[r1] = 1.f;
                }
            }
            BSYNC(BAR_CONS, 256);   // sP consumed before next tile's deposit

            BARRIVE(pb ? BAR_EMPTY1 : BAR_EMPTY0, 512);
            pb ^= 1;
        }
    }
}

// ---------------- L5: total consumption per metabolite ------------------------
__global__ void k_totcons(const int* __restrict__ met_sub,
                          const int* __restrict__ rxn_sub,
                          const float* __restrict__ sto_sub)
{
    int e = blockIdx.x * blockDim.x + threadIdx.x;
    if (e >= E_SUB) return;
    float c = sto_sub[e] * g_v[rxn_sub[e]] * DT;
    atomicAdd(&g_totcons[met_sub[e]], c);
}

// ---------------- L6: per-rxn min scale ---------------------------------------
__global__ void k_rscale(const float* __restrict__ x,
                         const int* __restrict__ met_sub,
                         const int* __restrict__ rxn_sub)
{
    int e = blockIdx.x * blockDim.x + threadIdx.x;
    if (e >= E_SUB) return;
    int   m    = met_sub[e];
    float tot  = g_totcons[m];
    float conc = x[m * 8 + 3];
    float sc   = (tot > 1e-12f) ? fminf(conc / tot, 1.0f) : 1.0f;
    atomicMin(reinterpret_cast<int*>(&g_rscale[rxn_sub[e]]), __float_as_int(sc));
}

// ---------------- L7: contributions + tail re-zero ----------------------------
__global__ void k_contrib(const int* __restrict__ met_sub,
                          const int* __restrict__ rxn_sub,
                          const float* __restrict__ sto_sub,
                          const int* __restrict__ met_prod,
                          const int* __restrict__ rxn_prod,
                          const float* __restrict__ sto_prod,
                          float* __restrict__ out)
{
    int blk = blockIdx.x, tid = threadIdx.x;
    if (blk < CONTRIB_B) {
        int i = blk * 256 + tid;
        if (i >= E_SUB + E_PROD) return;
        int m, r; float sto;
        if (i < E_SUB) {
            m = met_sub[i];  r = rxn_sub[i];  sto = -sto_sub[i];
        } else {
            int e = i - E_SUB;
            m = met_prod[e]; r = rxn_prod[e]; sto = sto_prod[e];
        }
        atomicAdd(&out[m], sto * g_v[r] * g_rscale[r]);
    } else {
        int i = (blk - CONTRIB_B) * 256 + tid;
        int stride = (gridDim.x - CONTRIB_B) * 256;
        for (int p = i; p < N_RXN; p += stride) g_cnt[p] = 0;
        for (int p = i; p < NB1; p += stride) g_sstate[p] = 0ULL;
    }
}

// ---------------- launch ------------------------------------------------------
extern "C" void kernel_launch(void* const* d_in, const int* in_sizes, int n_in,
                              void* d_out, int out_size)
{
    const float* x        = (const float*)d_in[0];
    const int*   met_sub  = (const int*)  d_in[1];
    const int*   rxn_sub  = (const int*)  d_in[2];
    const float* sto_sub  = (const float*)d_in[3];
    const int*   met_prod = (const int*)  d_in[4];
    const int*   rxn_prod = (const int*)  d_in[5];
    const float* sto_prod = (const float*)d_in[6];
    const float* W1       = (const float*)d_in[7];
    const float* b1       = (const float*)d_in[8];
    const float* W2       = (const float*)d_in[9];
    const float* b2       = (const float*)d_in[10];
    const float* V1       = (const float*)d_in[11];
    const float* c1       = (const float*)d_in[12];
    const float* V2       = (const float*)d_in[13];
    const float* c2       = (const float*)d_in[14];
    const float* log_k    = (const float*)d_in[15];
    float* out = (float*)d_out;

    cudaFuncSetAttribute(k2_gemm, cudaFuncAttributeMaxDynamicSharedMemorySize,
                         K2_SMEM_BYTES);

    k_hist_init<<<HIST_B + HIDDEN + 1 + 256, 256>>>(rxn_sub, W2, V1, b2, out);
    k_scan_lb<<<NB1, SCAN_BS>>>();
    k_scatter<<<(E_SUB + 255) / 256, 256>>>(rxn_sub);
    k2_gemm<<<K2_GRID, K2_THREADS, K2_SMEM_BYTES>>>(x, met_sub, sto_sub,
                                                    W1, b1, c1, V2, c2, log_k);
    k_totcons<<<(E_SUB + 255) / 256, 256>>>(met_sub, rxn_sub, sto_sub);
    k_rscale<<<(E_SUB + 255) / 256, 256>>>(x, met_sub, rxn_sub);
    k_contrib<<<CONTRIB_B + 128, 256>>>(met_sub, rxn_sub, sto_sub,
                                        met_prod, rxn_prod, sto_prod, out);
}